// round 4
// baseline (speedup 1.0000x reference)
#include <cuda_runtime.h>
#include <cuda_fp16.h>
#include <cstdint>

#define NMAX 100000
#define EMAX 1000000

// ---------------- scratch ----------------
__device__ int    g_deg[NMAX];
__device__ int    g_rowptr[NMAX + 1];
__device__ int    g_cursor[NMAX];
__device__ float  g_invdeg[NMAX];
__device__ int    g_eidx[EMAX];
__device__ float  g_xs[(size_t)NMAX * 64];   // x @ Ws1
__device__ float  g_xn[(size_t)NMAX * 64];   // x @ Wn1
__device__ __half g_hh[(size_t)NMAX * 64];   // h (fp16)
__device__ float  g_hn[(size_t)NMAX * 32];   // h @ Wn2

// ---------------- mma helper (fp16 in, fp32 acc; sm_80 feature, no 'a' gate) --------
__device__ __forceinline__ void mma_f16(float c[4], uint32_t a0, uint32_t a1,
                                        uint32_t a2, uint32_t a3,
                                        uint32_t b0, uint32_t b1) {
    asm volatile(
        "mma.sync.aligned.m16n8k16.row.col.f32.f16.f16.f32 "
        "{%0,%1,%2,%3}, {%4,%5,%6,%7}, {%8,%9}, {%0,%1,%2,%3};"
        : "+f"(c[0]), "+f"(c[1]), "+f"(c[2]), "+f"(c[3])
        : "r"(a0), "r"(a1), "r"(a2), "r"(a3), "r"(b0), "r"(b1));
}

// ---------------- CSR build ----------------
__global__ void k_zero_deg(int n) {
    int i = blockIdx.x * blockDim.x + threadIdx.x;
    if (i < n) g_deg[i] = 0;
}

__global__ void k_count(const int* __restrict__ dst, int e) {
    int i = blockIdx.x * blockDim.x + threadIdx.x;
    if (i < e) atomicAdd(&g_deg[dst[i]], 1);
}

// single-block chunked exclusive scan over degrees
__global__ void __launch_bounds__(1024) k_scan(int n, int e) {
    __shared__ int s[1024];
    int tid = threadIdx.x;
    int C = (n + 1023) >> 10;
    int lo = tid * C;
    int hi = lo + C; if (hi > n) hi = n;
    int sum = 0;
    for (int i = lo; i < hi; i++) sum += g_deg[i];
    s[tid] = sum;
    __syncthreads();
#pragma unroll
    for (int off = 1; off < 1024; off <<= 1) {
        int t = (tid >= off) ? s[tid - off] : 0;
        __syncthreads();
        s[tid] += t;
        __syncthreads();
    }
    int run = s[tid] - sum;
    for (int i = lo; i < hi; i++) {
        g_rowptr[i] = run;
        g_cursor[i] = run;
        int d = g_deg[i];
        g_invdeg[i] = 1.0f / (float)(d > 1 ? d : 1);
        run += d;
    }
    if (tid == 0) g_rowptr[n] = e;
}

__global__ void k_scatter(const int* __restrict__ src, const int* __restrict__ dst, int e) {
    int i = blockIdx.x * blockDim.x + threadIdx.x;
    if (i < e) {
        int d = dst[i];
        int p = atomicAdd(&g_cursor[d], 1);
        g_eidx[p] = src[i];
    }
}

// ---------------- layer-1 GEMM (fp16 mma): [xs|xn] = x @ [Ws1|Wn1] ----------------
// CTA: 256 thr, 128 rows x 128 cols. warps 4(M) x 2(N): warp tile 32 rows x 64 cols.
// smem pitch 72 halves (144B) -> conflict-free fragments (bank = 4g+t).
#define LHP 72

__global__ void __launch_bounds__(256) k_hgemm1(
    const float* __restrict__ x, const float* __restrict__ ws,
    const float* __restrict__ wn, int n)
{
    __shared__ __half As[128 * LHP];   // A: [row][k]  128x64
    __shared__ __half Bs[128 * LHP];   // B: [ncol][k] 128x64
    int tid = threadIdx.x, wid = tid >> 5, lane = tid & 31;
    int n0 = blockIdx.x * 128;

    // A fill: 128 rows x 32 float2 -> half2
    for (int idx = tid; idx < 4096; idx += 256) {
        int r = idx >> 5, q = idx & 31;
        int node = n0 + r;
        float2 v = make_float2(0.f, 0.f);
        if (node < n) v = ((const float2*)x)[(size_t)node * 32 + q];
        *(__half2*)&As[r * LHP + 2 * q] = __float22half2_rn(v);
    }
    // B fill (transpose): Bs[nn][k] = Ws1[k][nn] (nn<64) / Wn1[k][nn-64]
    for (int idx = tid; idx < 4096; idx += 256) {
        int k = idx >> 6, nn = idx & 63;
        Bs[nn * LHP + k]        = __float2half_rn(ws[idx]);
        Bs[(64 + nn) * LHP + k] = __float2half_rn(wn[idx]);
    }
    __syncthreads();

    int wm = wid & 3, wq = wid >> 2;
    int g = lane >> 2, t = lane & 3;
    float acc[2][8][4];
#pragma unroll
    for (int m = 0; m < 2; m++)
#pragma unroll
        for (int nt = 0; nt < 8; nt++)
#pragma unroll
            for (int i = 0; i < 4; i++) acc[m][nt][i] = 0.f;

#pragma unroll
    for (int ks = 0; ks < 4; ks++) {
        int k0 = ks * 16;
        uint32_t a[2][4];
#pragma unroll
        for (int m = 0; m < 2; m++) {
            int rb = wm * 32 + m * 16 + g;
            a[m][0] = *(const uint32_t*)&As[rb * LHP + k0 + 2 * t];
            a[m][1] = *(const uint32_t*)&As[(rb + 8) * LHP + k0 + 2 * t];
            a[m][2] = *(const uint32_t*)&As[rb * LHP + k0 + 2 * t + 8];
            a[m][3] = *(const uint32_t*)&As[(rb + 8) * LHP + k0 + 2 * t + 8];
        }
#pragma unroll
        for (int nt = 0; nt < 8; nt++) {
            int nc = wq * 64 + nt * 8 + g;
            uint32_t b0 = *(const uint32_t*)&Bs[nc * LHP + k0 + 2 * t];
            uint32_t b1 = *(const uint32_t*)&Bs[nc * LHP + k0 + 2 * t + 8];
            mma_f16(acc[0][nt], a[0][0], a[0][1], a[0][2], a[0][3], b0, b1);
            mma_f16(acc[1][nt], a[1][0], a[1][1], a[1][2], a[1][3], b0, b1);
        }
    }

    float* dstb = (wq == 0) ? g_xs : g_xn;
#pragma unroll
    for (int m = 0; m < 2; m++) {
        int r0 = n0 + wm * 32 + m * 16 + g;
        int r1 = r0 + 8;
#pragma unroll
        for (int nt = 0; nt < 8; nt++) {
            int col = nt * 8 + 2 * t;
            if (r0 < n) *(float2*)&dstb[(size_t)r0 * 64 + col] =
                make_float2(acc[m][nt][0], acc[m][nt][1]);
            if (r1 < n) *(float2*)&dstb[(size_t)r1 * 64 + col] =
                make_float2(acc[m][nt][2], acc[m][nt][3]);
        }
    }
}

// ---------------- layer-1 aggregation: h = relu(xs + b1 + invdeg * sum(xn[src])) ----
__global__ void k_agg1(const float* __restrict__ bias, int n) {
    int warp = (blockIdx.x * blockDim.x + threadIdx.x) >> 5;
    int lane = threadIdx.x & 31;
    if (warp >= n) return;
    int start = g_rowptr[warp], end = g_rowptr[warp + 1];
    const float2* xn2 = (const float2*)g_xn;
    float ax = 0.f, ay = 0.f;
    int e = start;
    for (; e + 4 <= end; e += 4) {
        int s0 = g_eidx[e], s1 = g_eidx[e + 1], s2 = g_eidx[e + 2], s3 = g_eidx[e + 3];
        float2 a = xn2[(size_t)s0 * 32 + lane];
        float2 b = xn2[(size_t)s1 * 32 + lane];
        float2 c = xn2[(size_t)s2 * 32 + lane];
        float2 d = xn2[(size_t)s3 * 32 + lane];
        ax += (a.x + b.x) + (c.x + d.x);
        ay += (a.y + b.y) + (c.y + d.y);
    }
    for (; e < end; e++) {
        int s = g_eidx[e];
        float2 a = xn2[(size_t)s * 32 + lane];
        ax += a.x; ay += a.y;
    }
    float id = g_invdeg[warp];
    float2 xs = ((const float2*)g_xs)[(size_t)warp * 32 + lane];
    float b0 = __ldg(&bias[2 * lane]);
    float b1 = __ldg(&bias[2 * lane + 1]);
    float hx = fmaxf(xs.x + b0 + ax * id, 0.f);
    float hy = fmaxf(xs.y + b1 + ay * id, 0.f);
    ((__half2*)g_hh)[(size_t)warp * 32 + lane] = __floats2half2_rn(hx, hy);
}

// ---------------- layer-2 GEMM (fp16 mma): [out|hn] = h @ [Ws2|Wn2] ----------------
// CTA: 256 thr, 128 rows x 64 cols. warps 4(M) x 2(N): warp tile 32 rows x 32 cols.
__global__ void __launch_bounds__(256) k_hgemm2(
    const float* __restrict__ ws, const float* __restrict__ wn,
    const float* __restrict__ bias, float* __restrict__ out, int n)
{
    __shared__ __half As[128 * LHP];  // 128x64
    __shared__ __half Bs[64 * LHP];   // 64 ncols x 64 k
    int tid = threadIdx.x, wid = tid >> 5, lane = tid & 31;
    int n0 = blockIdx.x * 128;

    // A fill from g_hh (already fp16): 128 rows x 32 half2
    for (int idx = tid; idx < 4096; idx += 256) {
        int r = idx >> 5, q = idx & 31;
        int node = n0 + r;
        uint32_t v = 0;
        if (node < n) v = ((const uint32_t*)g_hh)[(size_t)node * 32 + q];
        *(uint32_t*)&As[r * LHP + 2 * q] = v;
    }
    // B fill (transpose): Bs[nn][k] = Ws2[k][nn] (nn<32) / Wn2[k][nn-32]
    for (int idx = tid; idx < 2048; idx += 256) {
        int k = idx >> 5, nn = idx & 31;
        Bs[nn * LHP + k]        = __float2half_rn(ws[idx]);
        Bs[(32 + nn) * LHP + k] = __float2half_rn(wn[idx]);
    }
    __syncthreads();

    int wm = wid & 3, wq = wid >> 2;
    int g = lane >> 2, t = lane & 3;
    float acc[2][4][4];
#pragma unroll
    for (int m = 0; m < 2; m++)
#pragma unroll
        for (int nt = 0; nt < 4; nt++)
#pragma unroll
            for (int i = 0; i < 4; i++) acc[m][nt][i] = 0.f;

#pragma unroll
    for (int ks = 0; ks < 4; ks++) {
        int k0 = ks * 16;
        uint32_t a[2][4];
#pragma unroll
        for (int m = 0; m < 2; m++) {
            int rb = wm * 32 + m * 16 + g;
            a[m][0] = *(const uint32_t*)&As[rb * LHP + k0 + 2 * t];
            a[m][1] = *(const uint32_t*)&As[(rb + 8) * LHP + k0 + 2 * t];
            a[m][2] = *(const uint32_t*)&As[rb * LHP + k0 + 2 * t + 8];
            a[m][3] = *(const uint32_t*)&As[(rb + 8) * LHP + k0 + 2 * t + 8];
        }
#pragma unroll
        for (int nt = 0; nt < 4; nt++) {
            int nc = wq * 32 + nt * 8 + g;
            uint32_t b0 = *(const uint32_t*)&Bs[nc * LHP + k0 + 2 * t];
            uint32_t b1 = *(const uint32_t*)&Bs[nc * LHP + k0 + 2 * t + 8];
            mma_f16(acc[0][nt], a[0][0], a[0][1], a[0][2], a[0][3], b0, b1);
            mma_f16(acc[1][nt], a[1][0], a[1][1], a[1][2], a[1][3], b0, b1);
        }
    }

#pragma unroll
    for (int m = 0; m < 2; m++) {
        int r0 = n0 + wm * 32 + m * 16 + g;
        int r1 = r0 + 8;
#pragma unroll
        for (int nt = 0; nt < 4; nt++) {
            int col = nt * 8 + 2 * t;   // 0..31 within the half
            if (wq == 0) {
                float b0 = __ldg(&bias[col]);
                float b1 = __ldg(&bias[col + 1]);
                if (r0 < n) *(float2*)&out[(size_t)r0 * 32 + col] =
                    make_float2(acc[m][nt][0] + b0, acc[m][nt][1] + b1);
                if (r1 < n) *(float2*)&out[(size_t)r1 * 32 + col] =
                    make_float2(acc[m][nt][2] + b0, acc[m][nt][3] + b1);
            } else {
                if (r0 < n) *(float2*)&g_hn[(size_t)r0 * 32 + col] =
                    make_float2(acc[m][nt][0], acc[m][nt][1]);
                if (r1 < n) *(float2*)&g_hn[(size_t)r1 * 32 + col] =
                    make_float2(acc[m][nt][2], acc[m][nt][3]);
            }
        }
    }
}

// ---------------- layer-2 aggregation: out += invdeg * sum(hn[src]) ----------------
__global__ void k_agg2(float* __restrict__ out, int n) {
    int warp = (blockIdx.x * blockDim.x + threadIdx.x) >> 5;
    int lane = threadIdx.x & 31;
    if (warp >= n) return;
    int start = g_rowptr[warp], end = g_rowptr[warp + 1];
    float acc = 0.f;
    int e = start;
    for (; e + 4 <= end; e += 4) {
        int s0 = g_eidx[e], s1 = g_eidx[e + 1], s2 = g_eidx[e + 2], s3 = g_eidx[e + 3];
        float a = g_hn[(size_t)s0 * 32 + lane];
        float b = g_hn[(size_t)s1 * 32 + lane];
        float c = g_hn[(size_t)s2 * 32 + lane];
        float d = g_hn[(size_t)s3 * 32 + lane];
        acc += (a + b) + (c + d);
    }
    for (; e < end; e++) {
        int s = g_eidx[e];
        acc += g_hn[(size_t)s * 32 + lane];
    }
    out[(size_t)warp * 32 + lane] += acc * g_invdeg[warp];
}

// ---------------- launcher ----------------
extern "C" void kernel_launch(void* const* d_in, const int* in_sizes, int n_in,
                              void* d_out, int out_size) {
    const float* x   = (const float*)d_in[0];
    const int*   src = (const int*)d_in[1];
    const int*   dst = (const int*)d_in[2];
    const float* ws1 = (const float*)d_in[3];
    const float* wn1 = (const float*)d_in[4];
    const float* b1  = (const float*)d_in[5];
    const float* ws2 = (const float*)d_in[6];
    const float* wn2 = (const float*)d_in[7];
    const float* b2  = (const float*)d_in[8];
    float* out = (float*)d_out;

    int N = in_sizes[0] / 64;
    int E = in_sizes[1];
    int tiles = (N + 127) >> 7;

    k_zero_deg<<<(N + 255) / 256, 256>>>(N);          // 1
    k_count<<<(E + 255) / 256, 256>>>(dst, E);        // 2
    k_scan<<<1, 1024>>>(N, E);                        // 3
    k_hgemm1<<<tiles, 256>>>(x, ws1, wn1, N);         // 4 (profiled slot)
    k_scatter<<<(E + 255) / 256, 256>>>(src, dst, E); // 5
    k_agg1<<<(N + 7) / 8, 256>>>(b1, N);              // 6
    k_hgemm2<<<tiles, 256>>>(ws2, wn2, b2, out, N);   // 7
    k_agg2<<<(N + 7) / 8, 256>>>(out, N);             // 8
}

// round 5
// speedup vs baseline: 2.8440x; 2.8440x over previous
#include <cuda_runtime.h>
#include <cuda_fp16.h>
#include <cstdint>

#define NMAX 100000
#define EMAX 1000000

// ---------------- scratch ----------------
__device__ int    g_deg[NMAX];
__device__ int    g_rowptr[NMAX + 1];
__device__ int    g_cursor[NMAX];
__device__ float  g_invdeg[NMAX];
__device__ int    g_bsums[128];
__device__ int    g_boff[128];
__device__ int    g_eidx[EMAX];
__device__ float  g_xs[(size_t)NMAX * 64];   // x @ Ws1
__device__ float  g_xn[(size_t)NMAX * 64];   // x @ Wn1
__device__ __half g_hh[(size_t)NMAX * 64];   // h (fp16)
__device__ float  g_hn[(size_t)NMAX * 32];   // h @ Wn2

// ---------------- mma / cp.async helpers (sm_80-era PTX, no 'a' gate) ----------------
__device__ __forceinline__ void mma_f16(float c[4], uint32_t a0, uint32_t a1,
                                        uint32_t a2, uint32_t a3,
                                        uint32_t b0, uint32_t b1) {
    asm volatile(
        "mma.sync.aligned.m16n8k16.row.col.f32.f16.f16.f32 "
        "{%0,%1,%2,%3}, {%4,%5,%6,%7}, {%8,%9}, {%0,%1,%2,%3};"
        : "+f"(c[0]), "+f"(c[1]), "+f"(c[2]), "+f"(c[3])
        : "r"(a0), "r"(a1), "r"(a2), "r"(a3), "r"(b0), "r"(b1));
}
__device__ __forceinline__ void cp16(uint32_t saddr, const void* g) {
    asm volatile("cp.async.ca.shared.global [%0], [%1], 16;" :: "r"(saddr), "l"(g));
}
#define CP_COMMIT() asm volatile("cp.async.commit_group;" ::: "memory")

__device__ __forceinline__ uint32_t h2u(__half2 h) {
    return *reinterpret_cast<uint32_t*>(&h);
}

// ---------------- CSR build ----------------
__global__ void k_zero_deg(int n) {
    int i = blockIdx.x * blockDim.x + threadIdx.x;
    if (i < n) g_deg[i] = 0;
}

__global__ void k_count(const int* __restrict__ dst, int e) {
    int i = blockIdx.x * blockDim.x + threadIdx.x;
    if (i < e) atomicAdd(&g_deg[dst[i]], 1);
}

__global__ void k_scan1(int n) {
    __shared__ int s[1024];
    int tid = threadIdx.x;
    int i = blockIdx.x * 1024 + tid;
    int v = (i < n) ? g_deg[i] : 0;
    s[tid] = v;
    __syncthreads();
#pragma unroll
    for (int off = 1; off < 1024; off <<= 1) {
        int t = (tid >= off) ? s[tid - off] : 0;
        __syncthreads();
        s[tid] += t;
        __syncthreads();
    }
    if (i < n) g_rowptr[i] = s[tid] - v;
    if (tid == 1023) g_bsums[blockIdx.x] = s[1023];
}

__global__ void k_scan2(int nb) {
    __shared__ int s[128];
    int tid = threadIdx.x;
    int v = (tid < nb) ? g_bsums[tid] : 0;
    s[tid] = v;
    __syncthreads();
#pragma unroll
    for (int off = 1; off < 128; off <<= 1) {
        int t = (tid >= off) ? s[tid - off] : 0;
        __syncthreads();
        s[tid] += t;
        __syncthreads();
    }
    g_boff[tid] = s[tid] - v;
}

__global__ void k_scan3(int n, int e) {
    int i = blockIdx.x * 1024 + threadIdx.x;
    if (i < n) {
        int rp = g_rowptr[i] + g_boff[blockIdx.x];
        g_rowptr[i] = rp;
        g_cursor[i] = rp;
        int d = g_deg[i];
        g_invdeg[i] = 1.0f / (float)(d > 1 ? d : 1);
    }
    if (i == 0) g_rowptr[n] = e;
}

__global__ void k_scatter(const int* __restrict__ src, const int* __restrict__ dst, int e) {
    int i = blockIdx.x * blockDim.x + threadIdx.x;
    if (i < e) {
        int d = dst[i];
        int p = atomicAdd(&g_cursor[d], 1);
        g_eidx[p] = src[i];
    }
}

// ---------------- layer-1 GEMM (persistent + cp.async): [xs|xn] = x @ [Ws1|Wn1] ----
// grid=296 persistent. CTA: 256 thr. tile 128 rows x 128 cols; warps 4(M)x2(N), 32x64.
// B fp16 smem (pitch 72 halves). A fp32 smem double-buffered (pitch 68 floats, 272B row).
#define LHP 72
#define LAF 68
static constexpr int HG1_SMEM = 128 * LHP * 2 + 2 * 128 * LAF * 4;  // 18432 + 69632

__global__ void __launch_bounds__(256, 2) k_hgemm1(
    const float* __restrict__ x, const float* __restrict__ ws,
    const float* __restrict__ wn, int n, int ntiles)
{
    extern __shared__ char smraw[];
    __half* Bs = (__half*)smraw;                       // [128][LHP]
    float*  Af = (float*)(smraw + 128 * LHP * 2);      // [2][128][LAF]
    int tid = threadIdx.x, wid = tid >> 5, lane = tid & 31;

    if (blockIdx.x >= (unsigned)ntiles) return;

    // B fill (once): Bs[nn][k] = Ws1[k][nn], Bs[64+nn][k] = Wn1[k][nn]
    for (int idx = tid; idx < 4096; idx += 256) {
        int k = idx >> 6, nn = idx & 63;
        Bs[nn * LHP + k]        = __float2half_rn(ws[idx]);
        Bs[(64 + nn) * LHP + k] = __float2half_rn(wn[idx]);
    }

    // preload first A tile into buf 0
    {
        int base = blockIdx.x * 128;
        float* dst = Af;
        for (int c = tid; c < 2048; c += 256) {
            int r = c >> 4, q = c & 15;
            int node = base + r; if (node >= n) node = n - 1;
            uint32_t sa = (uint32_t)__cvta_generic_to_shared(dst + r * LAF + q * 4);
            cp16(sa, x + (size_t)node * 64 + q * 4);
        }
        CP_COMMIT();
    }

    int wm = wid & 3, wq = wid >> 2;
    int g = lane >> 2, t = lane & 3;
    int buf = 0;

    for (int tile = blockIdx.x; tile < ntiles; tile += gridDim.x, buf ^= 1) {
        int nxt = tile + gridDim.x;
        if (nxt < ntiles) {
            int base = nxt * 128;
            float* dst = Af + (buf ^ 1) * 128 * LAF;
            for (int c = tid; c < 2048; c += 256) {
                int r = c >> 4, q = c & 15;
                int node = base + r; if (node >= n) node = n - 1;
                uint32_t sa = (uint32_t)__cvta_generic_to_shared(dst + r * LAF + q * 4);
                cp16(sa, x + (size_t)node * 64 + q * 4);
            }
            CP_COMMIT();
            asm volatile("cp.async.wait_group 1;" ::: "memory");
        } else {
            asm volatile("cp.async.wait_group 0;" ::: "memory");
        }
        __syncthreads();

        const float* Ab = Af + buf * 128 * LAF;
        float acc[2][8][4];
#pragma unroll
        for (int m = 0; m < 2; m++)
#pragma unroll
            for (int nt = 0; nt < 8; nt++)
#pragma unroll
                for (int i = 0; i < 4; i++) acc[m][nt][i] = 0.f;

#pragma unroll
        for (int ks = 0; ks < 4; ks++) {
            int k0 = ks * 16;
            uint32_t a[2][4];
#pragma unroll
            for (int m = 0; m < 2; m++) {
                const float* r0p = Ab + (wm * 32 + m * 16 + g) * LAF + k0 + 2 * t;
                const float* r1p = r0p + 8 * LAF;
                a[m][0] = h2u(__float22half2_rn(*(const float2*)r0p));
                a[m][1] = h2u(__float22half2_rn(*(const float2*)r1p));
                a[m][2] = h2u(__float22half2_rn(*(const float2*)(r0p + 8)));
                a[m][3] = h2u(__float22half2_rn(*(const float2*)(r1p + 8)));
            }
#pragma unroll
            for (int nt = 0; nt < 8; nt++) {
                int nc = wq * 64 + nt * 8 + g;
                uint32_t b0 = *(const uint32_t*)&Bs[nc * LHP + k0 + 2 * t];
                uint32_t b1 = *(const uint32_t*)&Bs[nc * LHP + k0 + 2 * t + 8];
                mma_f16(acc[0][nt], a[0][0], a[0][1], a[0][2], a[0][3], b0, b1);
                mma_f16(acc[1][nt], a[1][0], a[1][1], a[1][2], a[1][3], b0, b1);
            }
        }

        int n0 = tile * 128;
        float* dstb = (wq == 0) ? g_xs : g_xn;
#pragma unroll
        for (int m = 0; m < 2; m++) {
            int r0 = n0 + wm * 32 + m * 16 + g;
            int r1 = r0 + 8;
#pragma unroll
            for (int nt = 0; nt < 8; nt++) {
                int col = nt * 8 + 2 * t;
                if (r0 < n) *(float2*)&dstb[(size_t)r0 * 64 + col] =
                    make_float2(acc[m][nt][0], acc[m][nt][1]);
                if (r1 < n) *(float2*)&dstb[(size_t)r1 * 64 + col] =
                    make_float2(acc[m][nt][2], acc[m][nt][3]);
            }
        }
        __syncthreads();   // protect buffer reuse
    }
}

// ---------------- layer-1 aggregation: h = relu(xs + b1 + invdeg * sum(xn[src])) ----
__global__ void k_agg1(const float* __restrict__ bias, int n) {
    int warp = (blockIdx.x * blockDim.x + threadIdx.x) >> 5;
    int lane = threadIdx.x & 31;
    if (warp >= n) return;
    int start = g_rowptr[warp], end = g_rowptr[warp + 1];
    const float2* xn2 = (const float2*)g_xn;
    float ax = 0.f, ay = 0.f;
    int e = start;
    for (; e + 4 <= end; e += 4) {
        int s0 = g_eidx[e], s1 = g_eidx[e + 1], s2 = g_eidx[e + 2], s3 = g_eidx[e + 3];
        float2 a = xn2[(size_t)s0 * 32 + lane];
        float2 b = xn2[(size_t)s1 * 32 + lane];
        float2 c = xn2[(size_t)s2 * 32 + lane];
        float2 d = xn2[(size_t)s3 * 32 + lane];
        ax += (a.x + b.x) + (c.x + d.x);
        ay += (a.y + b.y) + (c.y + d.y);
    }
    for (; e < end; e++) {
        int s = g_eidx[e];
        float2 a = xn2[(size_t)s * 32 + lane];
        ax += a.x; ay += a.y;
    }
    float id = g_invdeg[warp];
    float2 xs = ((const float2*)g_xs)[(size_t)warp * 32 + lane];
    float b0 = __ldg(&bias[2 * lane]);
    float b1 = __ldg(&bias[2 * lane + 1]);
    float hx = fmaxf(xs.x + b0 + ax * id, 0.f);
    float hy = fmaxf(xs.y + b1 + ay * id, 0.f);
    ((__half2*)g_hh)[(size_t)warp * 32 + lane] = __floats2half2_rn(hx, hy);
}

// ---------------- layer-2 GEMM (persistent + cp.async): [out|hn] = h @ [Ws2|Wn2] ----
// static smem 46KB. warps 4(M)x2(N), warp 32 rows x 32 cols.
__global__ void __launch_bounds__(256, 2) k_hgemm2(
    const float* __restrict__ ws, const float* __restrict__ wn,
    const float* __restrict__ bias, float* __restrict__ out, int n, int ntiles)
{
    __shared__ __half Bs[64 * LHP];
    __shared__ __half As[2][128 * LHP];
    int tid = threadIdx.x, wid = tid >> 5, lane = tid & 31;

    if (blockIdx.x >= (unsigned)ntiles) return;

    // B fill: Bs[nn][k] = Ws2[k][nn] (nn<32) / Wn2[k][nn-32]
    for (int idx = tid; idx < 2048; idx += 256) {
        int k = idx >> 5, nn = idx & 31;
        Bs[nn * LHP + k]        = __float2half_rn(ws[idx]);
        Bs[(32 + nn) * LHP + k] = __float2half_rn(wn[idx]);
    }

    {
        int base = blockIdx.x * 128;
        for (int c = tid; c < 1024; c += 256) {
            int r = c >> 3, q = c & 7;
            int node = base + r; if (node >= n) node = n - 1;
            uint32_t sa = (uint32_t)__cvta_generic_to_shared(&As[0][r * LHP + q * 8]);
            cp16(sa, g_hh + (size_t)node * 64 + q * 8);
        }
        CP_COMMIT();
    }

    int wm = wid & 3, wq = wid >> 2;
    int g = lane >> 2, t = lane & 3;
    int buf = 0;

    for (int tile = blockIdx.x; tile < ntiles; tile += gridDim.x, buf ^= 1) {
        int nxt = tile + gridDim.x;
        if (nxt < ntiles) {
            int base = nxt * 128;
            for (int c = tid; c < 1024; c += 256) {
                int r = c >> 3, q = c & 7;
                int node = base + r; if (node >= n) node = n - 1;
                uint32_t sa = (uint32_t)__cvta_generic_to_shared(&As[buf ^ 1][r * LHP + q * 8]);
                cp16(sa, g_hh + (size_t)node * 64 + q * 8);
            }
            CP_COMMIT();
            asm volatile("cp.async.wait_group 1;" ::: "memory");
        } else {
            asm volatile("cp.async.wait_group 0;" ::: "memory");
        }
        __syncthreads();

        const __half* Ab = As[buf];
        float acc[2][4][4];
#pragma unroll
        for (int m = 0; m < 2; m++)
#pragma unroll
            for (int nt = 0; nt < 4; nt++)
#pragma unroll
                for (int i = 0; i < 4; i++) acc[m][nt][i] = 0.f;

#pragma unroll
        for (int ks = 0; ks < 4; ks++) {
            int k0 = ks * 16;
            uint32_t a[2][4];
#pragma unroll
            for (int m = 0; m < 2; m++) {
                int rb = wm * 32 + m * 16 + g;
                a[m][0] = *(const uint32_t*)&Ab[rb * LHP + k0 + 2 * t];
                a[m][1] = *(const uint32_t*)&Ab[(rb + 8) * LHP + k0 + 2 * t];
                a[m][2] = *(const uint32_t*)&Ab[rb * LHP + k0 + 2 * t + 8];
                a[m][3] = *(const uint32_t*)&Ab[(rb + 8) * LHP + k0 + 2 * t + 8];
            }
#pragma unroll
            for (int nt = 0; nt < 4; nt++) {
                int nc = wq * 32 + nt * 8 + g;
                uint32_t b0 = *(const uint32_t*)&Bs[nc * LHP + k0 + 2 * t];
                uint32_t b1 = *(const uint32_t*)&Bs[nc * LHP + k0 + 2 * t + 8];
                mma_f16(acc[0][nt], a[0][0], a[0][1], a[0][2], a[0][3], b0, b1);
                mma_f16(acc[1][nt], a[1][0], a[1][1], a[1][2], a[1][3], b0, b1);
            }
        }

        int n0 = tile * 128;
#pragma unroll
        for (int m = 0; m < 2; m++) {
            int r0 = n0 + wm * 32 + m * 16 + g;
            int r1 = r0 + 8;
#pragma unroll
            for (int nt = 0; nt < 4; nt++) {
                int col = nt * 8 + 2 * t;
                if (wq == 0) {
                    float b0 = __ldg(&bias[col]);
                    float b1 = __ldg(&bias[col + 1]);
                    if (r0 < n) *(float2*)&out[(size_t)r0 * 32 + col] =
                        make_float2(acc[m][nt][0] + b0, acc[m][nt][1] + b1);
                    if (r1 < n) *(float2*)&out[(size_t)r1 * 32 + col] =
                        make_float2(acc[m][nt][2] + b0, acc[m][nt][3] + b1);
                } else {
                    if (r0 < n) *(float2*)&g_hn[(size_t)r0 * 32 + col] =
                        make_float2(acc[m][nt][0], acc[m][nt][1]);
                    if (r1 < n) *(float2*)&g_hn[(size_t)r1 * 32 + col] =
                        make_float2(acc[m][nt][2], acc[m][nt][3]);
                }
            }
        }
        __syncthreads();
    }
}

// ---------------- layer-2 aggregation: out += invdeg * sum(hn[src]) ----------------
__global__ void k_agg2(float* __restrict__ out, int n) {
    int warp = (blockIdx.x * blockDim.x + threadIdx.x) >> 5;
    int lane = threadIdx.x & 31;
    if (warp >= n) return;
    int start = g_rowptr[warp], end = g_rowptr[warp + 1];
    float acc = 0.f;
    int e = start;
    for (; e + 4 <= end; e += 4) {
        int s0 = g_eidx[e], s1 = g_eidx[e + 1], s2 = g_eidx[e + 2], s3 = g_eidx[e + 3];
        float a = g_hn[(size_t)s0 * 32 + lane];
        float b = g_hn[(size_t)s1 * 32 + lane];
        float c = g_hn[(size_t)s2 * 32 + lane];
        float d = g_hn[(size_t)s3 * 32 + lane];
        acc += (a + b) + (c + d);
    }
    for (; e < end; e++) {
        int s = g_eidx[e];
        acc += g_hn[(size_t)s * 32 + lane];
    }
    out[(size_t)warp * 32 + lane] += acc * g_invdeg[warp];
}

// ---------------- launcher ----------------
extern "C" void kernel_launch(void* const* d_in, const int* in_sizes, int n_in,
                              void* d_out, int out_size) {
    const float* x   = (const float*)d_in[0];
    const int*   src = (const int*)d_in[1];
    const int*   dst = (const int*)d_in[2];
    const float* ws1 = (const float*)d_in[3];
    const float* wn1 = (const float*)d_in[4];
    const float* b1  = (const float*)d_in[5];
    const float* ws2 = (const float*)d_in[6];
    const float* wn2 = (const float*)d_in[7];
    const float* b2  = (const float*)d_in[8];
    float* out = (float*)d_out;

    int N = in_sizes[0] / 64;
    int E = in_sizes[1];
    int ntiles = (N + 127) >> 7;
    int nb1 = (N + 1023) / 1024;
    int pgrid = 296;   // 2 persistent CTAs per SM

    cudaFuncSetAttribute(k_hgemm1, cudaFuncAttributeMaxDynamicSharedMemorySize, HG1_SMEM);

    k_zero_deg<<<(N + 255) / 256, 256>>>(N);                 // 1
    k_count<<<(E + 255) / 256, 256>>>(dst, E);               // 2
    k_scan1<<<nb1, 1024>>>(N);                               // 3
    k_hgemm1<<<pgrid, 256, HG1_SMEM>>>(x, ws1, wn1, N, ntiles); // 4 (profiled)
    k_scan2<<<1, 128>>>(nb1);                                // 5
    k_scan3<<<nb1, 1024>>>(N, E);                            // 6
    k_scatter<<<(E + 255) / 256, 256>>>(src, dst, E);        // 7
    k_agg1<<<(N + 7) / 8, 256>>>(b1, N);                     // 8
    k_hgemm2<<<pgrid, 256>>>(ws2, wn2, b2, out, N, ntiles);  // 9
    k_agg2<<<(N + 7) / 8, 256>>>(out, N);                    // 10
}